// round 17
// baseline (speedup 1.0000x reference)
#include <cuda_runtime.h>
#include <cuda_fp16.h>
#include <cstdint>

#define BATCH 2
#define SEQ 2048
#define IN_DIM 1024
#define HID_DIM 1024
#define NHEAD 16
#define HDIM 64
#define KDIM 1024
#define MROWS 4096

// ---------------------------------------------------------------------------
// Scratch (__device__ globals; allocation-free rule)
// ---------------------------------------------------------------------------
__device__ __half g_qin[MROWS * KDIM];
__device__ __half g_kin[MROWS * KDIM];
__device__ __half g_vin[MROWS * KDIM];
__device__ __half g_WqTh[HID_DIM * KDIM];
__device__ __half g_WkTh[HDIM * KDIM];
__device__ __half g_WvTh[HDIM * KDIM];
__device__ __half g_WoTh[IN_DIM * KDIM];
__device__ __half g_qPhi[MROWS * HID_DIM];
__device__ __half g_kPhi[MROWS * HDIM];
__device__ __half g_vPhi[MROWS * HDIM];
__device__ __half g_oh[MROWS * HID_DIM];

// ---------------------------------------------------------------------------
// PTX helpers (all sm_80-era; legal in family-generic PTX)
// ---------------------------------------------------------------------------
__device__ __forceinline__ uint32_t smem_u32(const void* p) {
    uint32_t a;
    asm("{ .reg .u64 t; cvta.to.shared.u64 t, %1; cvt.u32.u64 %0, t; }"
        : "=r"(a) : "l"(p));
    return a;
}
__device__ __forceinline__ void ldsm_x4(uint32_t* r, uint32_t addr) {
    asm volatile("ldmatrix.sync.aligned.m8n8.x4.shared.b16 {%0,%1,%2,%3}, [%4];"
                 : "=r"(r[0]), "=r"(r[1]), "=r"(r[2]), "=r"(r[3]) : "r"(addr));
}
__device__ __forceinline__ void ldsm_x4_t(uint32_t* r, uint32_t addr) {
    asm volatile("ldmatrix.sync.aligned.m8n8.x4.trans.shared.b16 {%0,%1,%2,%3}, [%4];"
                 : "=r"(r[0]), "=r"(r[1]), "=r"(r[2]), "=r"(r[3]) : "r"(addr));
}
__device__ __forceinline__ void mma_f16(float* d, const uint32_t* a,
                                        const uint32_t* b) {
    asm volatile(
        "mma.sync.aligned.m16n8k16.row.col.f32.f16.f16.f32 "
        "{%0,%1,%2,%3}, {%4,%5,%6,%7}, {%8,%9}, {%0,%1,%2,%3};"
        : "+f"(d[0]), "+f"(d[1]), "+f"(d[2]), "+f"(d[3])
        : "r"(a[0]), "r"(a[1]), "r"(a[2]), "r"(a[3]), "r"(b[0]), "r"(b[1]));
}
__device__ __forceinline__ void cp16(uint32_t smem, const void* g) {
    asm volatile("cp.async.cg.shared.global [%0], [%1], 16;"
                 :: "r"(smem), "l"(g));
}
__device__ __forceinline__ void cp_commit() {
    asm volatile("cp.async.commit_group;" ::: "memory");
}
__device__ __forceinline__ void cp_wait1() {
    asm volatile("cp.async.wait_group 1;" ::: "memory");
}
__device__ __forceinline__ void cp_wait0() {
    asm volatile("cp.async.wait_group 0;" ::: "memory");
}
__device__ __forceinline__ uint32_t pack_h2(float e, float o) {
    __half2 P(__float2half_rn(e), __float2half_rn(o));
    return *reinterpret_cast<uint32_t*>(&P);
}

// ---------------------------------------------------------------------------
// Fused prep: z=0..3 transpose weights fp32->fp16 (Wq,Wo,Wk,Wv),
//             z=4..6 convert inputs fp32->fp16 (q,k,v).
// block (32,8). grid (64, 32, 7).
// ---------------------------------------------------------------------------
struct PrepArgs {
    const float* W[4]; __half* T[4]; int N[4];
    const float4* X[3]; uint4* Y[3];
};
__global__ void prep_all(PrepArgs a, int n8)
{
    __shared__ float t[32][33];
    const int z = blockIdx.z;
    if (z < 4) {
        const int N = a.N[z];
        if ((int)blockIdx.x >= N / 32) return;
        const int n0 = blockIdx.x * 32, k0 = blockIdx.y * 32;
        const int tx = threadIdx.x, ty = threadIdx.y;
#pragma unroll
        for (int i = 0; i < 32; i += 8)
            t[ty + i][tx] = a.W[z][(size_t)(k0 + ty + i) * N + n0 + tx];
        __syncthreads();
#pragma unroll
        for (int i = 0; i < 32; i += 8)
            a.T[z][(size_t)(n0 + ty + i) * KDIM + k0 + tx] =
                __float2half_rn(t[tx][ty + i]);
    } else {
        const int s = z - 4;
        const int tid = threadIdx.y * 32 + threadIdx.x;
        const int i = (int)(blockIdx.y * gridDim.x + blockIdx.x) * 256 + tid;
        if (i < n8) {
            const float4 v0 = a.X[s][2 * i];
            const float4 v1 = a.X[s][2 * i + 1];
            uint4 H;
            H.x = pack_h2(v0.x, v0.y);
            H.y = pack_h2(v0.z, v0.w);
            H.z = pack_h2(v1.x, v1.y);
            H.w = pack_h2(v1.z, v1.w);
            a.Y[s][i] = H;
        }
    }
}

// ---------------------------------------------------------------------------
// 1-term fp16 GEMM core: C[M,N] = A[M,K] @ B[N,K]^T + bias
// cp.async double-buffered, K-chunk 64.
// EPI=0: fp32 out.  EPI=2: fp16 single out, scaled.
// ---------------------------------------------------------------------------
template <int BM, int BN, int EPI>
__device__ __forceinline__ void gemm_core_h1(
    const __half* A, const __half* Bh,
    const float* bias, float* C, __half* Chi,
    float scale, int Ntot, int m0, int n0, char* smem)
{
    constexpr int MF = BM / 64;
    constexpr int WN = BN / 2;
    constexpr int NF = WN / 8;
    constexpr uint32_t ROWB = 144;
    constexpr uint32_t OBH = BM * ROWB;
    constexpr uint32_t STAGE = (BM + BN) * ROWB;
    constexpr int NCH = KDIM / 64;

    const uint32_t uS = smem_u32(smem);
    const int tid = threadIdx.x;
    const int wid = tid >> 5, lane = tid & 31;
    const int warp_m = wid & 3, warp_n = wid >> 2;
    const int lrow = lane & 15;
    const int lcol = (lane >> 4) * 8;

    const __half* a_g = A + (size_t)m0 * KDIM;
    const __half* b_g = Bh + (size_t)n0 * KDIM;

    auto issue = [&](int ch, int buf) {
        const int k0 = ch * 64;
        const uint32_t base = uS + (uint32_t)buf * STAGE;
#pragma unroll
        for (int i = tid; i < BM * 8; i += 256) {
            const int r = i >> 3, c8 = (i & 7) * 8;
            cp16(base + (uint32_t)r * ROWB + c8 * 2,
                 a_g + (size_t)r * KDIM + k0 + c8);
        }
#pragma unroll
        for (int i = tid; i < BN * 8; i += 256) {
            const int r = i >> 3, c8 = (i & 7) * 8;
            cp16(base + OBH + (uint32_t)r * ROWB + c8 * 2,
                 b_g + (size_t)r * KDIM + k0 + c8);
        }
    };

    float acc[MF][NF][4] = {};

    issue(0, 0);
    cp_commit();

    for (int ch = 0; ch < NCH; ch++) {
        if (ch + 1 < NCH) {
            issue(ch + 1, (ch + 1) & 1);
            cp_commit();
            cp_wait1();
        } else {
            cp_wait0();
        }
        __syncthreads();

        const uint32_t base = uS + (uint32_t)(ch & 1) * STAGE;
#pragma unroll
        for (int ks = 0; ks < 4; ks++) {
            const int kk = ks * 16 + lcol;
            uint32_t ah[MF][4];
#pragma unroll
            for (int mf = 0; mf < MF; mf++) {
                const int row = warp_m * (BM / 4) + mf * 16 + lrow;
                ldsm_x4(ah[mf], base + (uint32_t)row * ROWB + kk * 2);
            }
            uint32_t bh[NF][2];
#pragma unroll
            for (int p = 0; p < NF / 2; p++) {
                const int row = warp_n * WN + p * 16 + lrow;
                uint32_t r4[4];
                ldsm_x4(r4, base + OBH + (uint32_t)row * ROWB + kk * 2);
                bh[2 * p][0] = r4[0]; bh[2 * p][1] = r4[2];
                bh[2 * p + 1][0] = r4[1]; bh[2 * p + 1][1] = r4[3];
            }
#pragma unroll
            for (int mf = 0; mf < MF; mf++)
#pragma unroll
                for (int nf = 0; nf < NF; nf++)
                    mma_f16(acc[mf][nf], ah[mf], bh[nf]);
        }
        __syncthreads();
    }

    const int gid = lane >> 2, t4 = lane & 3;
#pragma unroll
    for (int mf = 0; mf < MF; mf++) {
        const int row = m0 + warp_m * (BM / 4) + mf * 16 + gid;
#pragma unroll
        for (int nf = 0; nf < NF; nf++) {
            const int col = n0 + warp_n * WN + nf * 8 + t4 * 2;
            const float b0 = bias[col], b1 = bias[col + 1];
            if (EPI == 0) {
                float2 o0 = make_float2(acc[mf][nf][0] + b0, acc[mf][nf][1] + b1);
                float2 o1 = make_float2(acc[mf][nf][2] + b0, acc[mf][nf][3] + b1);
                *(float2*)(C + (size_t)row * Ntot + col) = o0;
                *(float2*)(C + (size_t)(row + 8) * Ntot + col) = o1;
            } else {
                *(uint32_t*)(Chi + (size_t)row * Ntot + col) =
                    pack_h2((acc[mf][nf][0] + b0) * scale,
                            (acc[mf][nf][1] + b1) * scale);
                *(uint32_t*)(Chi + (size_t)(row + 8) * Ntot + col) =
                    pack_h2((acc[mf][nf][2] + b0) * scale,
                            (acc[mf][nf][3] + b1) * scale);
            }
        }
    }
}

// ---------------------------------------------------------------------------
// Merged Q/K/V projection launch. grid (8, 32, 3):
//   z=0: Q-proj 128x128 tiles (all CTAs)
//   z=1/2: K/V-proj 128x64 tiles (x==0 CTAs only; 32 each)
// ---------------------------------------------------------------------------
struct ProjArgs {
    const __half *qA, *qBh; const float* qb; __half* qC;
    const __half *kvA[2], *kvBh[2];
    const float* kvb[2]; __half* kvC[2];
};
__global__ __launch_bounds__(256) void gemm_proj_all(ProjArgs a)
{
    extern __shared__ char smem[];
    const int z = blockIdx.z;
    if (z == 0) {
        gemm_core_h1<128, 128, 2>(a.qA, a.qBh, a.qb,
                                  nullptr, a.qC, 1.0f / 32.0f, HID_DIM,
                                  blockIdx.y * 128, blockIdx.x * 128, smem);
    } else {
        if (blockIdx.x != 0) return;
        const int s = z - 1;
        gemm_core_h1<128, 64, 2>(a.kvA[s], a.kvBh[s],
                                 a.kvb[s], nullptr, a.kvC[s], 1.0f, HDIM,
                                 blockIdx.y * 128, 0, smem);
    }
}

// O-projection: 1-term fp16, fp32 epilogue -> d_out
__global__ __launch_bounds__(256) void gemm_o(
    const __half* __restrict__ A, const __half* __restrict__ Bh,
    const float* __restrict__ bias, float* __restrict__ C)
{
    extern __shared__ char smem[];
    gemm_core_h1<128, 128, 0>(A, Bh, bias, C, nullptr, 1.0f, IN_DIM,
                              blockIdx.y * 128, blockIdx.x * 128, smem);
}

// ---------------------------------------------------------------------------
// Tensor-core MQA attention, pure single-fp16:
//   scores = Q·K (1 term);  PV = P·V (1 term)
// Epilogue: single fp16 normalized output.
// ---------------------------------------------------------------------------
__global__ __launch_bounds__(256) void mqa_attn_mma(
    const __half* __restrict__ Qhi,
    const __half* __restrict__ Khi, const __half* __restrict__ Vhi,
    __half* __restrict__ Oh)
{
    constexpr uint32_t ROWB = 144;
    constexpr uint32_t ST0 = 128 * ROWB;
    constexpr uint32_t STG = 128 * ROWB;
    constexpr uint32_t VHI = 64 * ROWB;
    constexpr int NCH = SEQ / 64;

    extern __shared__ char smc[];
    const uint32_t uS = smem_u32(smc);

    const int tid = threadIdx.x, wid = tid >> 5, lane = tid & 31;
    const int h = blockIdx.y, b = blockIdx.z;
    const int q0 = blockIdx.x * 128;
    const size_t qrow0 = (size_t)b * SEQ + q0;
    const int lrow = lane & 15;
    const int lcol = (lane >> 4) * 8;

    const __half* kh_g = Khi + (size_t)b * SEQ * HDIM;
    const __half* vh_g = Vhi + (size_t)b * SEQ * HDIM;

    auto issue = [&](int ch, int buf) {
        const int k0 = ch * 64;
        const uint32_t base = uS + ST0 + (uint32_t)buf * STG;
#pragma unroll
        for (int i = tid; i < 64 * 8; i += 256) {
            const int r = i >> 3, c8 = (i & 7) * 8;
            const uint32_t so = (uint32_t)r * ROWB + c8 * 2;
            const size_t g = (size_t)(k0 + r) * HDIM + c8;
            cp16(base + so, kh_g + g);
            cp16(base + VHI + so, vh_g + g);
        }
    };

    issue(0, 0);
    cp_commit();
    {
        const __half* qh_g = Qhi + qrow0 * HID_DIM + h * HDIM;
#pragma unroll
        for (int i = tid; i < 128 * 8; i += 256) {
            const int r = i >> 3, c8 = (i & 7) * 8;
            const uint32_t so = (uint32_t)r * ROWB + c8 * 2;
            *(uint4*)(smc + so) = *(const uint4*)(qh_g + (size_t)r * HID_DIM + c8);
        }
    }
    __syncthreads();
    uint32_t qh[4][4];
#pragma unroll
    for (int ks = 0; ks < 4; ks++) {
        const uint32_t off = (uint32_t)(wid * 16 + lrow) * ROWB + (ks * 16 + lcol) * 2;
        ldsm_x4(qh[ks], uS + off);
    }

    float m1 = -1e30f, m2 = -1e30f, lp1 = 0.0f, lp2 = 0.0f;
    float oacc[8][4] = {};

    for (int ch = 0; ch < NCH; ch++) {
        if (ch + 1 < NCH) {
            issue(ch + 1, (ch + 1) & 1);
            cp_commit();
            cp_wait1();
        } else {
            cp_wait0();
        }
        __syncthreads();

        const uint32_t base = uS + ST0 + (uint32_t)(ch & 1) * STG;

        float sc[8][4] = {};
#pragma unroll
        for (int ks = 0; ks < 4; ks++) {
#pragma unroll
            for (int p = 0; p < 4; p++) {
                const uint32_t off =
                    (uint32_t)(p * 16 + lrow) * ROWB + (ks * 16 + lcol) * 2;
                uint32_t rh[4];
                ldsm_x4(rh, base + off);
                uint32_t b0[2] = {rh[0], rh[2]}, b1[2] = {rh[1], rh[3]};
                mma_f16(sc[2 * p], qh[ks], b0);
                mma_f16(sc[2 * p + 1], qh[ks], b1);
            }
        }

        float mx1 = m1, mx2 = m2;
#pragma unroll
        for (int nf = 0; nf < 8; nf++) {
            mx1 = fmaxf(mx1, fmaxf(sc[nf][0], sc[nf][1]));
            mx2 = fmaxf(mx2, fmaxf(sc[nf][2], sc[nf][3]));
        }
        mx1 = fmaxf(mx1, __shfl_xor_sync(0xffffffffu, mx1, 1));
        mx1 = fmaxf(mx1, __shfl_xor_sync(0xffffffffu, mx1, 2));
        mx2 = fmaxf(mx2, __shfl_xor_sync(0xffffffffu, mx2, 1));
        mx2 = fmaxf(mx2, __shfl_xor_sync(0xffffffffu, mx2, 2));
        const float a1 = __expf(m1 - mx1);
        const float a2 = __expf(m2 - mx2);
        m1 = mx1; m2 = mx2;

        float s1 = 0.0f, s2 = 0.0f;
        uint32_t pr1[8], pr2[8];
#pragma unroll
        for (int nf = 0; nf < 8; nf++) {
            const float p0 = __expf(sc[nf][0] - mx1);
            const float p1 = __expf(sc[nf][1] - mx1);
            const float p2 = __expf(sc[nf][2] - mx2);
            const float p3 = __expf(sc[nf][3] - mx2);
            s1 += p0 + p1; s2 += p2 + p3;
            pr1[nf] = pack_h2(p0, p1);
            pr2[nf] = pack_h2(p2, p3);
        }
        lp1 = lp1 * a1 + s1;
        lp2 = lp2 * a2 + s2;
#pragma unroll
        for (int nf = 0; nf < 8; nf++) {
            oacc[nf][0] *= a1; oacc[nf][1] *= a1;
            oacc[nf][2] *= a2; oacc[nf][3] *= a2;
        }

#pragma unroll
        for (int ks = 0; ks < 4; ks++) {
            uint32_t pa[4] = {pr1[2 * ks], pr2[2 * ks],
                              pr1[2 * ks + 1], pr2[2 * ks + 1]};
#pragma unroll
            for (int p = 0; p < 4; p++) {
                const uint32_t off =
                    (uint32_t)(ks * 16 + lrow) * ROWB + (p * 16 + lcol) * 2;
                uint32_t rh[4];
                ldsm_x4_t(rh, base + VHI + off);
                uint32_t b0[2] = {rh[0], rh[1]}, b1[2] = {rh[2], rh[3]};
                mma_f16(oacc[2 * p], pa, b0);
                mma_f16(oacc[2 * p + 1], pa, b1);
            }
        }
        __syncthreads();
    }

    lp1 += __shfl_xor_sync(0xffffffffu, lp1, 1);
    lp1 += __shfl_xor_sync(0xffffffffu, lp1, 2);
    lp2 += __shfl_xor_sync(0xffffffffu, lp2, 1);
    lp2 += __shfl_xor_sync(0xffffffffu, lp2, 2);
    const float i1 = 1.0f / lp1, i2 = 1.0f / lp2;

    const size_t row1 = qrow0 + wid * 16 + (lane >> 2);
    const size_t row2 = row1 + 8;
#pragma unroll
    for (int nf = 0; nf < 8; nf++) {
        const int col = h * HDIM + nf * 8 + (lane & 3) * 2;
        *(uint32_t*)(Oh + row1 * HID_DIM + col) =
            pack_h2(oacc[nf][0] * i1, oacc[nf][1] * i1);
        *(uint32_t*)(Oh + row2 * HID_DIM + col) =
            pack_h2(oacc[nf][2] * i2, oacc[nf][3] * i2);
    }
}

static const int GEMMH_SMEM = 2 * (128 + 128) * 144;       // 73728
static const int ATTN_SMEM  = 128 * 144 + 2 * 128 * 144;   // 55296

// ---------------------------------------------------------------------------
// Launch
// ---------------------------------------------------------------------------
extern "C" void kernel_launch(void* const* d_in, const int* in_sizes, int n_in,
                              void* d_out, int out_size)
{
    const float* query = (const float*)d_in[0];
    const float* key   = (const float*)d_in[1];
    const float* value = (const float*)d_in[2];
    const float* Wq    = (const float*)d_in[3];
    const float* bq    = (const float*)d_in[4];
    const float* Wk    = (const float*)d_in[5];
    const float* bk    = (const float*)d_in[6];
    const float* Wv    = (const float*)d_in[7];
    const float* bv    = (const float*)d_in[8];
    const float* Wo    = (const float*)d_in[9];
    const float* bo    = (const float*)d_in[10];
    float* out = (float*)d_out;

    void *qi, *ki, *vi;
    void *wqh, *wkh, *wvh, *woh;
    void *qph, *kph, *vph, *oh;
    cudaGetSymbolAddress(&qi, g_qin);
    cudaGetSymbolAddress(&ki, g_kin);
    cudaGetSymbolAddress(&vi, g_vin);
    cudaGetSymbolAddress(&wqh, g_WqTh);
    cudaGetSymbolAddress(&wkh, g_WkTh);
    cudaGetSymbolAddress(&wvh, g_WvTh);
    cudaGetSymbolAddress(&woh, g_WoTh);
    cudaGetSymbolAddress(&qph, g_qPhi);
    cudaGetSymbolAddress(&kph, g_kPhi);
    cudaGetSymbolAddress(&vph, g_vPhi);
    cudaGetSymbolAddress(&oh, g_oh);

    cudaFuncSetAttribute((const void*)gemm_proj_all,
                         cudaFuncAttributeMaxDynamicSharedMemorySize, GEMMH_SMEM);
    cudaFuncSetAttribute((const void*)gemm_o,
                         cudaFuncAttributeMaxDynamicSharedMemorySize, GEMMH_SMEM);
    cudaFuncSetAttribute((const void*)mqa_attn_mma,
                         cudaFuncAttributeMaxDynamicSharedMemorySize, ATTN_SMEM);

    // --- fused prep: 4 weight transposes + 3 input converts, one launch ---
    {
        PrepArgs pa;
        pa.W[0] = Wq; pa.T[0] = (__half*)wqh; pa.N[0] = HID_DIM;
        pa.W[1] = Wo; pa.T[1] = (__half*)woh; pa.N[1] = IN_DIM;
        pa.W[2] = Wk; pa.T[2] = (__half*)wkh; pa.N[2] = HDIM;
        pa.W[3] = Wv; pa.T[3] = (__half*)wvh; pa.N[3] = HDIM;
        pa.X[0] = (const float4*)query; pa.Y[0] = (uint4*)qi;
        pa.X[1] = (const float4*)key;   pa.Y[1] = (uint4*)ki;
        pa.X[2] = (const float4*)value; pa.Y[2] = (uint4*)vi;
        const int n8 = MROWS * KDIM / 8;  // 524288; 2048 blocks of 256
        prep_all<<<dim3(64, 32, 7), dim3(32, 8)>>>(pa, n8);
    }
    // --- merged Q/K/V projections (1-term fp16; Q scaled 1/32) ---
    {
        ProjArgs a;
        a.qA = (const __half*)qi; a.qBh = (const __half*)wqh;
        a.qb = bq; a.qC = (__half*)qph;
        a.kvA[0] = (const __half*)ki; a.kvBh[0] = (const __half*)wkh;
        a.kvb[0] = bk; a.kvC[0] = (__half*)kph;
        a.kvA[1] = (const __half*)vi; a.kvBh[1] = (const __half*)wvh;
        a.kvb[1] = bv; a.kvC[1] = (__half*)vph;
        gemm_proj_all<<<dim3(HID_DIM / 128, MROWS / 128, 3), 256, GEMMH_SMEM>>>(a);
    }

    // --- tensor-core attention (pure fp16) ---
    {
        dim3 grid(SEQ / 128, NHEAD, BATCH);
        mqa_attn_mma<<<grid, 256, ATTN_SMEM>>>(
            (const __half*)qph, (const __half*)kph, (const __half*)vph,
            (__half*)oh);
    }

    // --- O-projection (1-term fp16) -> d_out ---
    gemm_o<<<dim3(IN_DIM / 128, MROWS / 128), 256, GEMMH_SMEM>>>(
        (const __half*)oh, (const __half*)woh, bo, out);
}